// round 12
// baseline (speedup 1.0000x reference)
#include <cuda_runtime.h>
#include <cuda_bf16.h>
#include <mma.h>

using namespace nvcuda;

#define N_USER 100000
#define N_ITEM 50000
#define NTOT   150000
#define EMB    64
#define FEAT   384
#define NNZ    2400000
#define EPS_F  1e-8f

// ---------------- device scratch (static, no allocations) ----------------
__device__ float          g_ego[NTOT * EMB];       // 38.4 MB fp32
__device__ __nv_bfloat162 g_ego16[NTOT * 32];      // 19.2 MB bf16
__device__ __nv_bfloat162 g_x1[NTOT * 32];
__device__ __nv_bfloat162 g_x2[NTOT * 32];
__device__ __nv_bfloat162 g_x3[NTOT * 32];
__device__ float g_norm[NTOT];
__device__ int   g_counts[NTOT];
__device__ int   g_rank[NNZ];                      // per-edge rank within row
__device__ int   g_rowptr[NTOT + 1];
__device__ int2  g_edges[NNZ];
__device__ int   g_bsum[256];
__device__ int   g_dhist[256];                     // degree histogram / cursor
__device__ int   g_dbase[256];                     // degree-bin bases
__device__ int   g_perm[NTOT];                     // rows sorted by degree

// ---------------- CSR build ----------------
__global__ void k_zero()
{
    int i = blockIdx.x * blockDim.x + threadIdx.x;
    if (i < NTOT) g_counts[i] = 0;
    if (i < 256) g_dhist[i] = 0;
}

__global__ void k_hist(const int* __restrict__ rows)
{
    int stride = gridDim.x * blockDim.x;
    for (int e = blockIdx.x * blockDim.x + threadIdx.x; e < NNZ; e += stride)
        g_rank[e] = atomicAdd(&g_counts[rows[e]], 1);
}

// ---- degree sort: 256-bin counting sort of rows by degree ----
__global__ void k_dhist()
{
    int i = blockIdx.x * blockDim.x + threadIdx.x;
    if (i < NTOT) atomicAdd(&g_dhist[min(g_counts[i], 255)], 1);
}

__global__ void k_dscan()
{
    __shared__ int sh[256];
    int t = threadIdx.x;
    int v = g_dhist[t];
    sh[t] = v;
    __syncthreads();
    for (int o = 1; o < 256; o <<= 1) {
        int u = (t >= o) ? sh[t - o] : 0;
        __syncthreads();
        if (t >= o) sh[t] += u;
        __syncthreads();
    }
    g_dbase[t] = sh[t] - v;
    g_dhist[t] = 0;               // reuse as bin cursor
}

__global__ void k_dperm()
{
    int i = blockIdx.x * blockDim.x + threadIdx.x;
    if (i < NTOT) {
        int b = min(g_counts[i], 255);
        int p = g_dbase[b] + atomicAdd(&g_dhist[b], 1);
        g_perm[p] = i;
    }
}

__global__ void k_scan1()
{
    __shared__ int sh[1024];
    int tid = threadIdx.x;
    int gid = blockIdx.x * 1024 + tid;
    int v = (gid < NTOT) ? g_counts[gid] : 0;
    sh[tid] = v;
    __syncthreads();
    for (int o = 1; o < 1024; o <<= 1) {
        int t = (tid >= o) ? sh[tid - o] : 0;
        __syncthreads();
        if (tid >= o) sh[tid] += t;
        __syncthreads();
    }
    if (gid < NTOT) g_rowptr[gid] = sh[tid] - v;
    if (tid == 1023) g_bsum[blockIdx.x] = sh[1023];
}

// scan3 computes its own block offset from g_bsum (scan2 folded in)
__global__ void k_scan3()
{
    __shared__ int s_off;
    int tid = threadIdx.x;
    if (tid < 32) {
        int acc = 0;
        for (int j = tid; j < (int)blockIdx.x; j += 32) acc += g_bsum[j];
#pragma unroll
        for (int o = 16; o; o >>= 1) acc += __shfl_xor_sync(0xffffffffu, acc, o);
        if (tid == 0) s_off = acc;
    }
    __syncthreads();
    int gid = blockIdx.x * 1024 + tid;
    if (gid < NTOT) g_rowptr[gid] += s_off;
    if (gid == 0) g_rowptr[NTOT] = NNZ;
}

__global__ void k_scatter(const int* __restrict__ rows,
                          const int* __restrict__ cols,
                          const float* __restrict__ vals)
{
    int stride = gridDim.x * blockDim.x;
    for (int e = blockIdx.x * blockDim.x + threadIdx.x; e < NNZ; e += stride) {
        int r = rows[e];
        int p = g_rowptr[r] + g_rank[e];
        g_edges[p] = make_int2(cols[e], __float_as_int(vals[e]));
    }
}

// ---------------- ego construction (fused norm + bf16) ----------------
__global__ void k_ego_user(const float* __restrict__ user,
                           const float* __restrict__ prompt)
{
    __shared__ float ps[EMB];
    int tid = threadIdx.x;
    if (tid < EMB) {
        float s = 0.f;
#pragma unroll
        for (int p = 0; p < 8; p++) s += prompt[p * EMB + tid];
        ps[tid] = s;
    }
    __syncthreads();
    int warp = (blockIdx.x * blockDim.x + tid) >> 5;
    int lane = tid & 31;
    if (warp >= N_USER) return;
    float2 u = ((const float2*)user)[warp * 32 + lane];
    float2 p2 = *(const float2*)&ps[lane * 2];
    float vx = u.x + p2.x, vy = u.y + p2.y;
    ((float2*)g_ego)[warp * 32 + lane] = make_float2(vx, vy);
    g_ego16[warp * 32 + lane] = __floats2bfloat162_rn(vx, vy);
    float s = vx * vx + vy * vy;
#pragma unroll
    for (int o = 16; o; o >>= 1) s += __shfl_xor_sync(0xffffffffu, s, o);
    if (lane == 0) g_norm[warp] = sqrtf(s);
}

// ---------------- item GEMM: wmma bf16 split-precision (R9-proven) -------
#define A_LD 24
#define B_LD 72
#define C_LD 68
#define SM_AHI 0
#define SM_ALO (SM_AHI + 128 * A_LD * 2)
#define SM_BHI (SM_ALO + 128 * A_LD * 2)
#define SM_BLO (SM_BHI + 16 * B_LD * 2)
#define SM_TOT (128 * C_LD * 4)

__global__ __launch_bounds__(256) void k_item(const float* __restrict__ fea,
                                              const float* __restrict__ w,
                                              const float* __restrict__ b)
{
    __shared__ __align__(16) char smem[SM_TOT];
    __nv_bfloat16* sAhi = (__nv_bfloat16*)(smem + SM_AHI);
    __nv_bfloat16* sAlo = (__nv_bfloat16*)(smem + SM_ALO);
    __nv_bfloat16* sBhi = (__nv_bfloat16*)(smem + SM_BHI);
    __nv_bfloat16* sBlo = (__nv_bfloat16*)(smem + SM_BLO);
    float* sC = (float*)smem;

    int tid = threadIdx.x;
    int wid = tid >> 5;
    int wm = wid & 3;
    int wn = wid >> 2;
    int row0 = blockIdx.x * 128;

    wmma::fragment<wmma::accumulator, 16, 16, 16, float> c[2][2];
#pragma unroll
    for (int i = 0; i < 2; i++)
#pragma unroll
        for (int j = 0; j < 2; j++) wmma::fill_fragment(c[i][j], 0.f);

    for (int k0 = 0; k0 < FEAT; k0 += 16) {
#pragma unroll
        for (int it = 0; it < 2; it++) {
            int f = tid + it * 256;
            int r = f >> 2, c4 = (f & 3) * 4;
            int gr = row0 + r;
            float4 v = (gr < N_ITEM) ? __ldg((const float4*)&fea[gr * FEAT + k0 + c4])
                                     : make_float4(0.f, 0.f, 0.f, 0.f);
            __nv_bfloat162 h0 = __floats2bfloat162_rn(v.x, v.y);
            __nv_bfloat162 h1 = __floats2bfloat162_rn(v.z, v.w);
            float2 hf0 = __bfloat1622float2(h0);
            float2 hf1 = __bfloat1622float2(h1);
            __nv_bfloat162 l0 = __floats2bfloat162_rn(v.x - hf0.x, v.y - hf0.y);
            __nv_bfloat162 l1 = __floats2bfloat162_rn(v.z - hf1.x, v.w - hf1.y);
            *(__nv_bfloat162*)&sAhi[r * A_LD + c4]     = h0;
            *(__nv_bfloat162*)&sAhi[r * A_LD + c4 + 2] = h1;
            *(__nv_bfloat162*)&sAlo[r * A_LD + c4]     = l0;
            *(__nv_bfloat162*)&sAlo[r * A_LD + c4 + 2] = l1;
        }
        {
            int r = tid >> 4, c4 = (tid & 15) * 4;
            float4 v = __ldg((const float4*)&w[(k0 + r) * EMB + c4]);
            __nv_bfloat162 h0 = __floats2bfloat162_rn(v.x, v.y);
            __nv_bfloat162 h1 = __floats2bfloat162_rn(v.z, v.w);
            float2 hf0 = __bfloat1622float2(h0);
            float2 hf1 = __bfloat1622float2(h1);
            __nv_bfloat162 l0 = __floats2bfloat162_rn(v.x - hf0.x, v.y - hf0.y);
            __nv_bfloat162 l1 = __floats2bfloat162_rn(v.z - hf1.x, v.w - hf1.y);
            *(__nv_bfloat162*)&sBhi[r * B_LD + c4]     = h0;
            *(__nv_bfloat162*)&sBhi[r * B_LD + c4 + 2] = h1;
            *(__nv_bfloat162*)&sBlo[r * B_LD + c4]     = l0;
            *(__nv_bfloat162*)&sBlo[r * B_LD + c4 + 2] = l1;
        }
        __syncthreads();

        wmma::fragment<wmma::matrix_a, 16, 16, 16, __nv_bfloat16, wmma::row_major> ahi[2], alo[2];
        wmma::fragment<wmma::matrix_b, 16, 16, 16, __nv_bfloat16, wmma::row_major> bhi[2], blo[2];
#pragma unroll
        for (int i = 0; i < 2; i++) {
            wmma::load_matrix_sync(ahi[i], sAhi + (wm * 32 + i * 16) * A_LD, A_LD);
            wmma::load_matrix_sync(alo[i], sAlo + (wm * 32 + i * 16) * A_LD, A_LD);
        }
#pragma unroll
        for (int j = 0; j < 2; j++) {
            wmma::load_matrix_sync(bhi[j], sBhi + wn * 32 + j * 16, B_LD);
            wmma::load_matrix_sync(blo[j], sBlo + wn * 32 + j * 16, B_LD);
        }
#pragma unroll
        for (int i = 0; i < 2; i++)
#pragma unroll
            for (int j = 0; j < 2; j++) {
                wmma::mma_sync(c[i][j], ahi[i], bhi[j], c[i][j]);
                wmma::mma_sync(c[i][j], ahi[i], blo[j], c[i][j]);
                wmma::mma_sync(c[i][j], alo[i], bhi[j], c[i][j]);
            }
        __syncthreads();
    }

#pragma unroll
    for (int i = 0; i < 2; i++)
#pragma unroll
        for (int j = 0; j < 2; j++)
            wmma::store_matrix_sync(&sC[(wm * 32 + i * 16) * C_LD + wn * 32 + j * 16],
                                    c[i][j], C_LD, wmma::mem_row_major);
    __syncthreads();

    int ty = tid >> 4;
    int tx = tid & 15;
#pragma unroll
    for (int r = 0; r < 8; r++) {
        int lr = ty * 8 + r;
        int gr = row0 + lr;
        float c0 = tanhf(sC[lr * C_LD + tx * 4 + 0] + b[tx * 4 + 0]);
        float c1 = tanhf(sC[lr * C_LD + tx * 4 + 1] + b[tx * 4 + 1]);
        float c2 = tanhf(sC[lr * C_LD + tx * 4 + 2] + b[tx * 4 + 2]);
        float c3 = tanhf(sC[lr * C_LD + tx * 4 + 3] + b[tx * 4 + 3]);
        float s = c0 * c0 + c1 * c1 + c2 * c2 + c3 * c3;
#pragma unroll
        for (int o = 1; o < 16; o <<= 1) s += __shfl_xor_sync(0xffffffffu, s, o);
        if (gr < N_ITEM) {
            int row = N_USER + gr;
            *(float4*)&g_ego[row * EMB + tx * 4] = make_float4(c0, c1, c2, c3);
            g_ego16[row * 32 + tx * 2 + 0] = __floats2bfloat162_rn(c0, c1);
            g_ego16[row * 32 + tx * 2 + 1] = __floats2bfloat162_rn(c2, c3);
            if (tx == 0) g_norm[row] = sqrtf(s);
        }
    }
}

// ---------------- fused SpMM + cosine-reweight, 4 rows/warp, batch-8 ------
// Exact R9 inner loop; rows assigned via degree-sorted permutation so the
// 4 rows per warp have near-equal lengths (ml ~= len).
__global__ __launch_bounds__(256) void k_layerA(const __nv_bfloat162* __restrict__ xin,
                                                __nv_bfloat162* __restrict__ xout)
{
    int gwarp = (blockIdx.x * blockDim.x + threadIdx.x) >> 5;
    int lane = threadIdx.x & 31;
    int gl   = lane & 7;
    int gb   = lane & 24;
    int pidx = gwarp * 4 + (lane >> 3);
    if (pidx >= NTOT) return;              // NTOT % 4 == 0: uniform warp exit
    int row = __ldg(&g_perm[pidx]);

    int s = g_rowptr[row];
    int len = g_rowptr[row + 1] - s;
    int ml = max(len, __shfl_xor_sync(0xffffffffu, len, 8));
    ml = max(ml, __shfl_xor_sync(0xffffffffu, ml, 16));

    const uint4* x4 = (const uint4*)xin;
    float a0 = 0.f, a1 = 0.f, a2 = 0.f, a3 = 0.f;
    float a4 = 0.f, a5 = 0.f, a6 = 0.f, a7 = 0.f;
    for (int base = 0; base < ml; base += 8) {
        int i = base + gl;
        int2 myed = (i < len) ? __ldg(&g_edges[s + i]) : make_int2(0, 0);
#pragma unroll
        for (int j = 0; j < 8; j++) {
            int c  = __shfl_sync(0xffffffffu, myed.x, gb + j);
            int vb = __shfl_sync(0xffffffffu, myed.y, gb + j);
            float v = __int_as_float(vb);
            uint4 q = __ldg(&x4[c * 8 + gl]);
            float2 f0 = __bfloat1622float2(*(__nv_bfloat162*)&q.x);
            float2 f1 = __bfloat1622float2(*(__nv_bfloat162*)&q.y);
            float2 f2 = __bfloat1622float2(*(__nv_bfloat162*)&q.z);
            float2 f3 = __bfloat1622float2(*(__nv_bfloat162*)&q.w);
            a0 += v * f0.x; a1 += v * f0.y;
            a2 += v * f1.x; a3 += v * f1.y;
            a4 += v * f2.x; a5 += v * f2.y;
            a6 += v * f3.x; a7 += v * f3.y;
        }
    }

    uint4 eq = ((const uint4*)g_ego16)[row * 8 + gl];
    float2 e0 = __bfloat1622float2(*(__nv_bfloat162*)&eq.x);
    float2 e1 = __bfloat1622float2(*(__nv_bfloat162*)&eq.y);
    float2 e2 = __bfloat1622float2(*(__nv_bfloat162*)&eq.z);
    float2 e3 = __bfloat1622float2(*(__nv_bfloat162*)&eq.w);
    float dot = a0 * e0.x + a1 * e0.y + a2 * e1.x + a3 * e1.y
              + a4 * e2.x + a5 * e2.y + a6 * e3.x + a7 * e3.y;
    float nn  = a0 * a0 + a1 * a1 + a2 * a2 + a3 * a3
              + a4 * a4 + a5 * a5 + a6 * a6 + a7 * a7;
#pragma unroll
    for (int o = 4; o; o >>= 1) {
        dot += __shfl_xor_sync(0xffffffffu, dot, o);
        nn  += __shfl_xor_sync(0xffffffffu, nn,  o);
    }
    float wgt = dot / fmaxf(sqrtf(nn) * g_norm[row], EPS_F);

    uint4 oq;
    *(__nv_bfloat162*)&oq.x = __floats2bfloat162_rn(wgt * a0, wgt * a1);
    *(__nv_bfloat162*)&oq.y = __floats2bfloat162_rn(wgt * a2, wgt * a3);
    *(__nv_bfloat162*)&oq.z = __floats2bfloat162_rn(wgt * a4, wgt * a5);
    *(__nv_bfloat162*)&oq.w = __floats2bfloat162_rn(wgt * a6, wgt * a7);
    ((uint4*)xout)[row * 8 + gl] = oq;
}

// final layer: SpMM + reweight + fused total sum  out = ego + x1 + x2 + x3 + x4
__global__ __launch_bounds__(256) void k_layerB(float* __restrict__ out)
{
    int gwarp = (blockIdx.x * blockDim.x + threadIdx.x) >> 5;
    int lane = threadIdx.x & 31;
    int gl   = lane & 7;
    int gb   = lane & 24;
    int pidx = gwarp * 4 + (lane >> 3);
    if (pidx >= NTOT) return;
    int row = __ldg(&g_perm[pidx]);

    int s = g_rowptr[row];
    int len = g_rowptr[row + 1] - s;
    int ml = max(len, __shfl_xor_sync(0xffffffffu, len, 8));
    ml = max(ml, __shfl_xor_sync(0xffffffffu, ml, 16));

    const uint4* x4 = (const uint4*)g_x3;
    float a0 = 0.f, a1 = 0.f, a2 = 0.f, a3 = 0.f;
    float a4 = 0.f, a5 = 0.f, a6 = 0.f, a7 = 0.f;
    for (int base = 0; base < ml; base += 8) {
        int i = base + gl;
        int2 myed = (i < len) ? __ldg(&g_edges[s + i]) : make_int2(0, 0);
#pragma unroll
        for (int j = 0; j < 8; j++) {
            int c  = __shfl_sync(0xffffffffu, myed.x, gb + j);
            int vb = __shfl_sync(0xffffffffu, myed.y, gb + j);
            float v = __int_as_float(vb);
            uint4 q = __ldg(&x4[c * 8 + gl]);
            float2 f0 = __bfloat1622float2(*(__nv_bfloat162*)&q.x);
            float2 f1 = __bfloat1622float2(*(__nv_bfloat162*)&q.y);
            float2 f2 = __bfloat1622float2(*(__nv_bfloat162*)&q.z);
            float2 f3 = __bfloat1622float2(*(__nv_bfloat162*)&q.w);
            a0 += v * f0.x; a1 += v * f0.y;
            a2 += v * f1.x; a3 += v * f1.y;
            a4 += v * f2.x; a5 += v * f2.y;
            a6 += v * f3.x; a7 += v * f3.y;
        }
    }

    int eidx = row * 16 + gl * 2;
    float4 ea = ((const float4*)g_ego)[eidx];
    float4 eb = ((const float4*)g_ego)[eidx + 1];
    float dot = a0 * ea.x + a1 * ea.y + a2 * ea.z + a3 * ea.w
              + a4 * eb.x + a5 * eb.y + a6 * eb.z + a7 * eb.w;
    float nn  = a0 * a0 + a1 * a1 + a2 * a2 + a3 * a3
              + a4 * a4 + a5 * a5 + a6 * a6 + a7 * a7;
#pragma unroll
    for (int o = 4; o; o >>= 1) {
        dot += __shfl_xor_sync(0xffffffffu, dot, o);
        nn  += __shfl_xor_sync(0xffffffffu, nn,  o);
    }
    float wgt = dot / fmaxf(sqrtf(nn) * g_norm[row], EPS_F);

    int idx = row * 8 + gl;
    uint4 q1 = ((const uint4*)g_x1)[idx];
    uint4 q2 = ((const uint4*)g_x2)[idx];
    uint4 q3 = ((const uint4*)g_x3)[idx];
    float2 p10 = __bfloat1622float2(*(__nv_bfloat162*)&q1.x);
    float2 p11 = __bfloat1622float2(*(__nv_bfloat162*)&q1.y);
    float2 p12 = __bfloat1622float2(*(__nv_bfloat162*)&q1.z);
    float2 p13 = __bfloat1622float2(*(__nv_bfloat162*)&q1.w);
    float2 p20 = __bfloat1622float2(*(__nv_bfloat162*)&q2.x);
    float2 p21 = __bfloat1622float2(*(__nv_bfloat162*)&q2.y);
    float2 p22 = __bfloat1622float2(*(__nv_bfloat162*)&q2.z);
    float2 p23 = __bfloat1622float2(*(__nv_bfloat162*)&q2.w);
    float2 p30 = __bfloat1622float2(*(__nv_bfloat162*)&q3.x);
    float2 p31 = __bfloat1622float2(*(__nv_bfloat162*)&q3.y);
    float2 p32 = __bfloat1622float2(*(__nv_bfloat162*)&q3.z);
    float2 p33 = __bfloat1622float2(*(__nv_bfloat162*)&q3.w);

    float4 ra, rb;
    ra.x = ea.x + p10.x + p20.x + p30.x + wgt * a0;
    ra.y = ea.y + p10.y + p20.y + p30.y + wgt * a1;
    ra.z = ea.z + p11.x + p21.x + p31.x + wgt * a2;
    ra.w = ea.w + p11.y + p21.y + p31.y + wgt * a3;
    rb.x = eb.x + p12.x + p22.x + p32.x + wgt * a4;
    rb.y = eb.y + p12.y + p22.y + p32.y + wgt * a5;
    rb.z = eb.z + p13.x + p23.x + p33.x + wgt * a6;
    rb.w = eb.w + p13.y + p23.y + p33.y + wgt * a7;
    ((float4*)out)[eidx]     = ra;
    ((float4*)out)[eidx + 1] = rb;
}

// ---------------- side stream (created at static-init; never destroyed) ----
namespace {
struct SideStream {
    cudaStream_t s = 0;
    cudaEvent_t fork = 0, join = 0;
    SideStream() {
        if (cudaStreamCreateWithFlags(&s, cudaStreamNonBlocking) != cudaSuccess) s = 0;
        if (cudaEventCreateWithFlags(&fork, cudaEventDisableTiming) != cudaSuccess) fork = 0;
        if (cudaEventCreateWithFlags(&join, cudaEventDisableTiming) != cudaSuccess) join = 0;
        if (!fork || !join) s = 0;
    }
};
SideStream g_ss;
}

// ---------------- launch ----------------
extern "C" void kernel_launch(void* const* d_in, const int* in_sizes, int n_in,
                              void* d_out, int out_size)
{
    const float* user   = (const float*)d_in[0];
    const float* item   = (const float*)d_in[1];
    const float* prompt = (const float*)d_in[2];
    const float* mw     = (const float*)d_in[3];
    const float* mb     = (const float*)d_in[4];
    const int*   rows   = (const int*)d_in[5];
    const int*   cols   = (const int*)d_in[6];
    const float* vals   = (const float*)d_in[7];
    float* out = (float*)d_out;

    void *p16, *p1, *p2, *p3;
    cudaGetSymbolAddress(&p16, g_ego16);
    cudaGetSymbolAddress(&p1,  g_x1);
    cudaGetSymbolAddress(&p2,  g_x2);
    cudaGetSymbolAddress(&p3,  g_x3);
    __nv_bfloat162* ego16 = (__nv_bfloat162*)p16;
    __nv_bfloat162* x1    = (__nv_bfloat162*)p1;
    __nv_bfloat162* x2    = (__nv_bfloat162*)p2;
    __nv_bfloat162* x3    = (__nv_bfloat162*)p3;

    const int SCAN_BLOCKS = (NTOT + 1023) / 1024;   // 147
    cudaStream_t sb = g_ss.s ? g_ss.s : (cudaStream_t)0;
    bool split = (g_ss.s != 0);

    if (split) {
        cudaEventRecord(g_ss.fork, 0);
        cudaStreamWaitEvent(g_ss.s, g_ss.fork, 0);
    }

    // chain A (stream 0): CSR build + degree sort
    k_zero   <<<(NTOT + 255) / 256, 256>>>();
    k_hist   <<<2048, 256>>>(rows);
    k_dhist  <<<(NTOT + 255) / 256, 256>>>();
    k_dscan  <<<1, 256>>>();
    k_dperm  <<<(NTOT + 255) / 256, 256>>>();
    k_scan1  <<<SCAN_BLOCKS, 1024>>>();
    k_scan3  <<<SCAN_BLOCKS, 1024>>>();
    k_scatter<<<2048, 256>>>(rows, cols, vals);

    // chain B (side stream): ego + norms + bf16 mirror
    k_ego_user<<<(N_USER * 32 + 255) / 256, 256, 0, sb>>>(user, prompt);
    k_item    <<<(N_ITEM + 127) / 128, 256, 0, sb>>>(item, mw, mb);

    if (split) {
        cudaEventRecord(g_ss.join, g_ss.s);
        cudaStreamWaitEvent(0, g_ss.join, 0);
    }

    // 4 propagation layers — degree-balanced 4 rows/warp, batch-8 gathers
    const int LB = (NTOT / 4 * 32 + 255) / 256;   // 4688 blocks
    k_layerA<<<LB, 256>>>(ego16, x1);
    k_layerA<<<LB, 256>>>(x1,    x2);
    k_layerA<<<LB, 256>>>(x2,    x3);
    k_layerB<<<LB, 256>>>(out);
}

// round 15
// speedup vs baseline: 1.2146x; 1.2146x over previous
#include <cuda_runtime.h>
#include <cuda_bf16.h>
#include <mma.h>

using namespace nvcuda;

#define N_USER 100000
#define N_ITEM 50000
#define NTOT   150000
#define EMB    64
#define FEAT   384
#define NNZ    2400000
#define EPS_F  1e-8f

// ---------------- device scratch (static, no allocations) ----------------
__device__ float          g_ego[NTOT * EMB];       // 38.4 MB fp32
__device__ __nv_bfloat162 g_ego16[NTOT * 32];      // 19.2 MB bf16
__device__ __nv_bfloat162 g_x1[NTOT * 32];
__device__ __nv_bfloat162 g_x2[NTOT * 32];
__device__ __nv_bfloat162 g_x3[NTOT * 32];
__device__ float g_norm[NTOT];
__device__ int   g_counts[NTOT];
__device__ int   g_rank[NNZ];                      // per-edge rank within row
__device__ int   g_rowptr[NTOT + 1];
__device__ int2  g_edges[NNZ];
__device__ int   g_bsum[256];

// ---------------- CSR build (R9 champion path) ----------------
__global__ void k_zero()
{
    int i = blockIdx.x * blockDim.x + threadIdx.x;
    if (i < NTOT) g_counts[i] = 0;
}

__global__ void k_hist(const int* __restrict__ rows)
{
    int stride = gridDim.x * blockDim.x;
    for (int e = blockIdx.x * blockDim.x + threadIdx.x; e < NNZ; e += stride)
        g_rank[e] = atomicAdd(&g_counts[rows[e]], 1);
}

__global__ void k_scan1()
{
    __shared__ int sh[1024];
    int tid = threadIdx.x;
    int gid = blockIdx.x * 1024 + tid;
    int v = (gid < NTOT) ? g_counts[gid] : 0;
    sh[tid] = v;
    __syncthreads();
    for (int o = 1; o < 1024; o <<= 1) {
        int t = (tid >= o) ? sh[tid - o] : 0;
        __syncthreads();
        if (tid >= o) sh[tid] += t;
        __syncthreads();
    }
    if (gid < NTOT) g_rowptr[gid] = sh[tid] - v;
    if (tid == 1023) g_bsum[blockIdx.x] = sh[1023];
}

__global__ void k_scan2(int nb)
{
    __shared__ int sh[256];
    int tid = threadIdx.x;
    int v = (tid < nb) ? g_bsum[tid] : 0;
    sh[tid] = v;
    __syncthreads();
    for (int o = 1; o < 256; o <<= 1) {
        int t = (tid >= o) ? sh[tid - o] : 0;
        __syncthreads();
        if (tid >= o) sh[tid] += t;
        __syncthreads();
    }
    g_bsum[tid] = sh[tid] - v;
}

__global__ void k_scan3()
{
    int gid = blockIdx.x * 1024 + threadIdx.x;
    if (gid < NTOT) g_rowptr[gid] += g_bsum[blockIdx.x];
    if (gid == 0) g_rowptr[NTOT] = NNZ;
}

// atomic-free scatter; int4-vectorized loads (4 edges/iter). Stores are
// rank-addressed, so processing order is irrelevant to the result.
__global__ void k_scatter(const int* __restrict__ rows,
                          const int* __restrict__ cols,
                          const float* __restrict__ vals)
{
    int stride = gridDim.x * blockDim.x;
    const int4* r4 = (const int4*)rows;
    const int4* c4 = (const int4*)cols;
    const int4* v4 = (const int4*)vals;
    const int4* k4 = (const int4*)g_rank;
    for (int e = blockIdx.x * blockDim.x + threadIdx.x; e < NNZ / 4; e += stride) {
        int4 r = __ldg(&r4[e]);
        int4 c = __ldg(&c4[e]);
        int4 v = __ldg(&v4[e]);
        int4 k = __ldg(&k4[e]);
        g_edges[g_rowptr[r.x] + k.x] = make_int2(c.x, v.x);
        g_edges[g_rowptr[r.y] + k.y] = make_int2(c.y, v.y);
        g_edges[g_rowptr[r.z] + k.z] = make_int2(c.z, v.z);
        g_edges[g_rowptr[r.w] + k.w] = make_int2(c.w, v.w);
    }
}

// ---------------- ego construction (fused norm + bf16) ----------------
__global__ void k_ego_user(const float* __restrict__ user,
                           const float* __restrict__ prompt)
{
    __shared__ float ps[EMB];
    int tid = threadIdx.x;
    if (tid < EMB) {
        float s = 0.f;
#pragma unroll
        for (int p = 0; p < 8; p++) s += prompt[p * EMB + tid];
        ps[tid] = s;
    }
    __syncthreads();
    int warp = (blockIdx.x * blockDim.x + tid) >> 5;
    int lane = tid & 31;
    if (warp >= N_USER) return;
    float2 u = ((const float2*)user)[warp * 32 + lane];
    float2 p2 = *(const float2*)&ps[lane * 2];
    float vx = u.x + p2.x, vy = u.y + p2.y;
    ((float2*)g_ego)[warp * 32 + lane] = make_float2(vx, vy);
    g_ego16[warp * 32 + lane] = __floats2bfloat162_rn(vx, vy);
    float s = vx * vx + vy * vy;
#pragma unroll
    for (int o = 16; o; o >>= 1) s += __shfl_xor_sync(0xffffffffu, s, o);
    if (lane == 0) g_norm[warp] = sqrtf(s);
}

// ---------------- item GEMM: wmma bf16 split-precision (R9-proven) -------
#define A_LD 24
#define B_LD 72
#define C_LD 68
#define SM_AHI 0
#define SM_ALO (SM_AHI + 128 * A_LD * 2)
#define SM_BHI (SM_ALO + 128 * A_LD * 2)
#define SM_BLO (SM_BHI + 16 * B_LD * 2)
#define SM_TOT (128 * C_LD * 4)

__global__ __launch_bounds__(256) void k_item(const float* __restrict__ fea,
                                              const float* __restrict__ w,
                                              const float* __restrict__ b)
{
    __shared__ __align__(16) char smem[SM_TOT];
    __nv_bfloat16* sAhi = (__nv_bfloat16*)(smem + SM_AHI);
    __nv_bfloat16* sAlo = (__nv_bfloat16*)(smem + SM_ALO);
    __nv_bfloat16* sBhi = (__nv_bfloat16*)(smem + SM_BHI);
    __nv_bfloat16* sBlo = (__nv_bfloat16*)(smem + SM_BLO);
    float* sC = (float*)smem;

    int tid = threadIdx.x;
    int wid = tid >> 5;
    int wm = wid & 3;
    int wn = wid >> 2;
    int row0 = blockIdx.x * 128;

    wmma::fragment<wmma::accumulator, 16, 16, 16, float> c[2][2];
#pragma unroll
    for (int i = 0; i < 2; i++)
#pragma unroll
        for (int j = 0; j < 2; j++) wmma::fill_fragment(c[i][j], 0.f);

    for (int k0 = 0; k0 < FEAT; k0 += 16) {
#pragma unroll
        for (int it = 0; it < 2; it++) {
            int f = tid + it * 256;
            int r = f >> 2, c4 = (f & 3) * 4;
            int gr = row0 + r;
            float4 v = (gr < N_ITEM) ? __ldg((const float4*)&fea[gr * FEAT + k0 + c4])
                                     : make_float4(0.f, 0.f, 0.f, 0.f);
            __nv_bfloat162 h0 = __floats2bfloat162_rn(v.x, v.y);
            __nv_bfloat162 h1 = __floats2bfloat162_rn(v.z, v.w);
            float2 hf0 = __bfloat1622float2(h0);
            float2 hf1 = __bfloat1622float2(h1);
            __nv_bfloat162 l0 = __floats2bfloat162_rn(v.x - hf0.x, v.y - hf0.y);
            __nv_bfloat162 l1 = __floats2bfloat162_rn(v.z - hf1.x, v.w - hf1.y);
            *(__nv_bfloat162*)&sAhi[r * A_LD + c4]     = h0;
            *(__nv_bfloat162*)&sAhi[r * A_LD + c4 + 2] = h1;
            *(__nv_bfloat162*)&sAlo[r * A_LD + c4]     = l0;
            *(__nv_bfloat162*)&sAlo[r * A_LD + c4 + 2] = l1;
        }
        {
            int r = tid >> 4, c4 = (tid & 15) * 4;
            float4 v = __ldg((const float4*)&w[(k0 + r) * EMB + c4]);
            __nv_bfloat162 h0 = __floats2bfloat162_rn(v.x, v.y);
            __nv_bfloat162 h1 = __floats2bfloat162_rn(v.z, v.w);
            float2 hf0 = __bfloat1622float2(h0);
            float2 hf1 = __bfloat1622float2(h1);
            __nv_bfloat162 l0 = __floats2bfloat162_rn(v.x - hf0.x, v.y - hf0.y);
            __nv_bfloat162 l1 = __floats2bfloat162_rn(v.z - hf1.x, v.w - hf1.y);
            *(__nv_bfloat162*)&sBhi[r * B_LD + c4]     = h0;
            *(__nv_bfloat162*)&sBhi[r * B_LD + c4 + 2] = h1;
            *(__nv_bfloat162*)&sBlo[r * B_LD + c4]     = l0;
            *(__nv_bfloat162*)&sBlo[r * B_LD + c4 + 2] = l1;
        }
        __syncthreads();

        wmma::fragment<wmma::matrix_a, 16, 16, 16, __nv_bfloat16, wmma::row_major> ahi[2], alo[2];
        wmma::fragment<wmma::matrix_b, 16, 16, 16, __nv_bfloat16, wmma::row_major> bhi[2], blo[2];
#pragma unroll
        for (int i = 0; i < 2; i++) {
            wmma::load_matrix_sync(ahi[i], sAhi + (wm * 32 + i * 16) * A_LD, A_LD);
            wmma::load_matrix_sync(alo[i], sAlo + (wm * 32 + i * 16) * A_LD, A_LD);
        }
#pragma unroll
        for (int j = 0; j < 2; j++) {
            wmma::load_matrix_sync(bhi[j], sBhi + wn * 32 + j * 16, B_LD);
            wmma::load_matrix_sync(blo[j], sBlo + wn * 32 + j * 16, B_LD);
        }
#pragma unroll
        for (int i = 0; i < 2; i++)
#pragma unroll
            for (int j = 0; j < 2; j++) {
                wmma::mma_sync(c[i][j], ahi[i], bhi[j], c[i][j]);
                wmma::mma_sync(c[i][j], ahi[i], blo[j], c[i][j]);
                wmma::mma_sync(c[i][j], alo[i], bhi[j], c[i][j]);
            }
        __syncthreads();
    }

#pragma unroll
    for (int i = 0; i < 2; i++)
#pragma unroll
        for (int j = 0; j < 2; j++)
            wmma::store_matrix_sync(&sC[(wm * 32 + i * 16) * C_LD + wn * 32 + j * 16],
                                    c[i][j], C_LD, wmma::mem_row_major);
    __syncthreads();

    int ty = tid >> 4;
    int tx = tid & 15;
#pragma unroll
    for (int r = 0; r < 8; r++) {
        int lr = ty * 8 + r;
        int gr = row0 + lr;
        float c0 = tanhf(sC[lr * C_LD + tx * 4 + 0] + b[tx * 4 + 0]);
        float c1 = tanhf(sC[lr * C_LD + tx * 4 + 1] + b[tx * 4 + 1]);
        float c2 = tanhf(sC[lr * C_LD + tx * 4 + 2] + b[tx * 4 + 2]);
        float c3 = tanhf(sC[lr * C_LD + tx * 4 + 3] + b[tx * 4 + 3]);
        float s = c0 * c0 + c1 * c1 + c2 * c2 + c3 * c3;
#pragma unroll
        for (int o = 1; o < 16; o <<= 1) s += __shfl_xor_sync(0xffffffffu, s, o);
        if (gr < N_ITEM) {
            int row = N_USER + gr;
            *(float4*)&g_ego[row * EMB + tx * 4] = make_float4(c0, c1, c2, c3);
            g_ego16[row * 32 + tx * 2 + 0] = __floats2bfloat162_rn(c0, c1);
            g_ego16[row * 32 + tx * 2 + 1] = __floats2bfloat162_rn(c2, c3);
            if (tx == 0) g_norm[row] = sqrtf(s);
        }
    }
}

// ---------------- fused SpMM + cosine-reweight, 4 rows/warp, batch-8 ------
// EXACT R9 form (champion) — do not touch.
__global__ __launch_bounds__(256) void k_layerA(const __nv_bfloat162* __restrict__ xin,
                                                __nv_bfloat162* __restrict__ xout)
{
    int gwarp = (blockIdx.x * blockDim.x + threadIdx.x) >> 5;
    int lane = threadIdx.x & 31;
    int gl   = lane & 7;
    int gb   = lane & 24;
    int row  = gwarp * 4 + (lane >> 3);
    if (row >= NTOT) return;

    int s = g_rowptr[row];
    int len = g_rowptr[row + 1] - s;
    int ml = max(len, __shfl_xor_sync(0xffffffffu, len, 8));
    ml = max(ml, __shfl_xor_sync(0xffffffffu, ml, 16));

    const uint4* x4 = (const uint4*)xin;
    float a0 = 0.f, a1 = 0.f, a2 = 0.f, a3 = 0.f;
    float a4 = 0.f, a5 = 0.f, a6 = 0.f, a7 = 0.f;
    for (int base = 0; base < ml; base += 8) {
        int i = base + gl;
        int2 myed = (i < len) ? __ldg(&g_edges[s + i]) : make_int2(0, 0);
#pragma unroll
        for (int j = 0; j < 8; j++) {
            int c  = __shfl_sync(0xffffffffu, myed.x, gb + j);
            int vb = __shfl_sync(0xffffffffu, myed.y, gb + j);
            float v = __int_as_float(vb);
            uint4 q = __ldg(&x4[c * 8 + gl]);
            float2 f0 = __bfloat1622float2(*(__nv_bfloat162*)&q.x);
            float2 f1 = __bfloat1622float2(*(__nv_bfloat162*)&q.y);
            float2 f2 = __bfloat1622float2(*(__nv_bfloat162*)&q.z);
            float2 f3 = __bfloat1622float2(*(__nv_bfloat162*)&q.w);
            a0 += v * f0.x; a1 += v * f0.y;
            a2 += v * f1.x; a3 += v * f1.y;
            a4 += v * f2.x; a5 += v * f2.y;
            a6 += v * f3.x; a7 += v * f3.y;
        }
    }

    uint4 eq = ((const uint4*)g_ego16)[row * 8 + gl];
    float2 e0 = __bfloat1622float2(*(__nv_bfloat162*)&eq.x);
    float2 e1 = __bfloat1622float2(*(__nv_bfloat162*)&eq.y);
    float2 e2 = __bfloat1622float2(*(__nv_bfloat162*)&eq.z);
    float2 e3 = __bfloat1622float2(*(__nv_bfloat162*)&eq.w);
    float dot = a0 * e0.x + a1 * e0.y + a2 * e1.x + a3 * e1.y
              + a4 * e2.x + a5 * e2.y + a6 * e3.x + a7 * e3.y;
    float nn  = a0 * a0 + a1 * a1 + a2 * a2 + a3 * a3
              + a4 * a4 + a5 * a5 + a6 * a6 + a7 * a7;
#pragma unroll
    for (int o = 4; o; o >>= 1) {
        dot += __shfl_xor_sync(0xffffffffu, dot, o);
        nn  += __shfl_xor_sync(0xffffffffu, nn,  o);
    }
    float wgt = dot / fmaxf(sqrtf(nn) * g_norm[row], EPS_F);

    uint4 oq;
    *(__nv_bfloat162*)&oq.x = __floats2bfloat162_rn(wgt * a0, wgt * a1);
    *(__nv_bfloat162*)&oq.y = __floats2bfloat162_rn(wgt * a2, wgt * a3);
    *(__nv_bfloat162*)&oq.z = __floats2bfloat162_rn(wgt * a4, wgt * a5);
    *(__nv_bfloat162*)&oq.w = __floats2bfloat162_rn(wgt * a6, wgt * a7);
    ((uint4*)xout)[row * 8 + gl] = oq;
}

// final layer: SpMM + reweight + fused total sum  out = ego + x1 + x2 + x3 + x4
__global__ __launch_bounds__(256) void k_layerB(float* __restrict__ out)
{
    int gwarp = (blockIdx.x * blockDim.x + threadIdx.x) >> 5;
    int lane = threadIdx.x & 31;
    int gl   = lane & 7;
    int gb   = lane & 24;
    int row  = gwarp * 4 + (lane >> 3);
    if (row >= NTOT) return;

    int s = g_rowptr[row];
    int len = g_rowptr[row + 1] - s;
    int ml = max(len, __shfl_xor_sync(0xffffffffu, len, 8));
    ml = max(ml, __shfl_xor_sync(0xffffffffu, ml, 16));

    const uint4* x4 = (const uint4*)g_x3;
    float a0 = 0.f, a1 = 0.f, a2 = 0.f, a3 = 0.f;
    float a4 = 0.f, a5 = 0.f, a6 = 0.f, a7 = 0.f;
    for (int base = 0; base < ml; base += 8) {
        int i = base + gl;
        int2 myed = (i < len) ? __ldg(&g_edges[s + i]) : make_int2(0, 0);
#pragma unroll
        for (int j = 0; j < 8; j++) {
            int c  = __shfl_sync(0xffffffffu, myed.x, gb + j);
            int vb = __shfl_sync(0xffffffffu, myed.y, gb + j);
            float v = __int_as_float(vb);
            uint4 q = __ldg(&x4[c * 8 + gl]);
            float2 f0 = __bfloat1622float2(*(__nv_bfloat162*)&q.x);
            float2 f1 = __bfloat1622float2(*(__nv_bfloat162*)&q.y);
            float2 f2 = __bfloat1622float2(*(__nv_bfloat162*)&q.z);
            float2 f3 = __bfloat1622float2(*(__nv_bfloat162*)&q.w);
            a0 += v * f0.x; a1 += v * f0.y;
            a2 += v * f1.x; a3 += v * f1.y;
            a4 += v * f2.x; a5 += v * f2.y;
            a6 += v * f3.x; a7 += v * f3.y;
        }
    }

    int eidx = row * 16 + gl * 2;
    float4 ea = ((const float4*)g_ego)[eidx];
    float4 eb = ((const float4*)g_ego)[eidx + 1];
    float dot = a0 * ea.x + a1 * ea.y + a2 * ea.z + a3 * ea.w
              + a4 * eb.x + a5 * eb.y + a6 * eb.z + a7 * eb.w;
    float nn  = a0 * a0 + a1 * a1 + a2 * a2 + a3 * a3
              + a4 * a4 + a5 * a5 + a6 * a6 + a7 * a7;
#pragma unroll
    for (int o = 4; o; o >>= 1) {
        dot += __shfl_xor_sync(0xffffffffu, dot, o);
        nn  += __shfl_xor_sync(0xffffffffu, nn,  o);
    }
    float wgt = dot / fmaxf(sqrtf(nn) * g_norm[row], EPS_F);

    int idx = row * 8 + gl;
    uint4 q1 = ((const uint4*)g_x1)[idx];
    uint4 q2 = ((const uint4*)g_x2)[idx];
    uint4 q3 = ((const uint4*)g_x3)[idx];
    float2 p10 = __bfloat1622float2(*(__nv_bfloat162*)&q1.x);
    float2 p11 = __bfloat1622float2(*(__nv_bfloat162*)&q1.y);
    float2 p12 = __bfloat1622float2(*(__nv_bfloat162*)&q1.z);
    float2 p13 = __bfloat1622float2(*(__nv_bfloat162*)&q1.w);
    float2 p20 = __bfloat1622float2(*(__nv_bfloat162*)&q2.x);
    float2 p21 = __bfloat1622float2(*(__nv_bfloat162*)&q2.y);
    float2 p22 = __bfloat1622float2(*(__nv_bfloat162*)&q2.z);
    float2 p23 = __bfloat1622float2(*(__nv_bfloat162*)&q2.w);
    float2 p30 = __bfloat1622float2(*(__nv_bfloat162*)&q3.x);
    float2 p31 = __bfloat1622float2(*(__nv_bfloat162*)&q3.y);
    float2 p32 = __bfloat1622float2(*(__nv_bfloat162*)&q3.z);
    float2 p33 = __bfloat1622float2(*(__nv_bfloat162*)&q3.w);

    float4 ra, rb;
    ra.x = ea.x + p10.x + p20.x + p30.x + wgt * a0;
    ra.y = ea.y + p10.y + p20.y + p30.y + wgt * a1;
    ra.z = ea.z + p11.x + p21.x + p31.x + wgt * a2;
    ra.w = ea.w + p11.y + p21.y + p31.y + wgt * a3;
    rb.x = eb.x + p12.x + p22.x + p32.x + wgt * a4;
    rb.y = eb.y + p12.y + p22.y + p32.y + wgt * a5;
    rb.z = eb.z + p13.x + p23.x + p33.x + wgt * a6;
    rb.w = eb.w + p13.y + p23.y + p33.y + wgt * a7;
    ((float4*)out)[eidx]     = ra;
    ((float4*)out)[eidx + 1] = rb;
}

// ---------------- side stream (created at static-init; never destroyed) ----
namespace {
struct SideStream {
    cudaStream_t s = 0;
    cudaEvent_t fork = 0, join = 0;
    SideStream() {
        if (cudaStreamCreateWithFlags(&s, cudaStreamNonBlocking) != cudaSuccess) s = 0;
        if (cudaEventCreateWithFlags(&fork, cudaEventDisableTiming) != cudaSuccess) fork = 0;
        if (cudaEventCreateWithFlags(&join, cudaEventDisableTiming) != cudaSuccess) join = 0;
        if (!fork || !join) s = 0;
    }
};
SideStream g_ss;
}

// ---------------- launch ----------------
extern "C" void kernel_launch(void* const* d_in, const int* in_sizes, int n_in,
                              void* d_out, int out_size)
{
    const float* user   = (const float*)d_in[0];
    const float* item   = (const float*)d_in[1];
    const float* prompt = (const float*)d_in[2];
    const float* mw     = (const float*)d_in[3];
    const float* mb     = (const float*)d_in[4];
    const int*   rows   = (const int*)d_in[5];
    const int*   cols   = (const int*)d_in[6];
    const float* vals   = (const float*)d_in[7];
    float* out = (float*)d_out;

    void *p16, *p1, *p2, *p3;
    cudaGetSymbolAddress(&p16, g_ego16);
    cudaGetSymbolAddress(&p1,  g_x1);
    cudaGetSymbolAddress(&p2,  g_x2);
    cudaGetSymbolAddress(&p3,  g_x3);
    __nv_bfloat162* ego16 = (__nv_bfloat162*)p16;
    __nv_bfloat162* x1    = (__nv_bfloat162*)p1;
    __nv_bfloat162* x2    = (__nv_bfloat162*)p2;
    __nv_bfloat162* x3    = (__nv_bfloat162*)p3;

    const int SCAN_BLOCKS = (NTOT + 1023) / 1024;   // 147
    cudaStream_t sb = g_ss.s ? g_ss.s : (cudaStream_t)0;
    bool split = (g_ss.s != 0);

    if (split) {
        cudaEventRecord(g_ss.fork, 0);
        cudaStreamWaitEvent(g_ss.s, g_ss.fork, 0);
    }

    // chain A (stream 0): CSR build (R9 path; scatter loads vectorized)
    k_zero   <<<(NTOT + 255) / 256, 256>>>();
    k_hist   <<<2048, 256>>>(rows);
    k_scan1  <<<SCAN_BLOCKS, 1024>>>();
    k_scan2  <<<1, 256>>>(SCAN_BLOCKS);
    k_scan3  <<<SCAN_BLOCKS, 1024>>>();
    k_scatter<<<2048, 256>>>(rows, cols, vals);

    // chain B (side stream): ego + norms + bf16 mirror
    k_ego_user<<<(N_USER * 32 + 255) / 256, 256, 0, sb>>>(user, prompt);
    k_item    <<<(N_ITEM + 127) / 128, 256, 0, sb>>>(item, mw, mb);

    if (split) {
        cudaEventRecord(g_ss.join, g_ss.s);
        cudaStreamWaitEvent(0, g_ss.join, 0);
    }

    // 4 propagation layers — four rows per warp, batch-8 gathers (R9)
    const int LB = (NTOT / 4 * 32 + 255) / 256;   // 4688 blocks
    k_layerA<<<LB, 256>>>(ego16, x1);
    k_layerA<<<LB, 256>>>(x1,    x2);
    k_layerA<<<LB, 256>>>(x2,    x3);
    k_layerB<<<LB, 256>>>(out);
}